// round 3
// baseline (speedup 1.0000x reference)
#include <cuda_runtime.h>

// Problem constants
#define BN 8
#define CC 64
#define HH 128
#define WW 128
#define NPIX (HH * WW)

// ---------------------------------------------------------------------------
// Scratch (device globals — no allocation allowed in kernel_launch)
// ---------------------------------------------------------------------------
__device__ float g_x0[BN * CC * NPIX];    // conv0 output
__device__ float g_out1[BN * CC * NPIX];  // depthwise + channel-attn output
__device__ float g_out2[BN * CC * NPIX];  // dynamic conv + leaky output
__device__ float g_mean[BN * CC];
__device__ float g_x2[BN * CC];

// ---------------------------------------------------------------------------
// Dense 3x3 conv, C=64 -> 64, pad 1.  Register-tiled:
//   block = 256 threads, tile 32(W) x 16(H), 8 output channels per block.
//   thread = 2 adjacent W pixels x 8 oc accumulators.
//   Weights (8 oc x 64 ic x 9) preloaded to smem once; read as LDS.128 bcast.
//   Input streamed through smem in 8-ic chunks.
// add_res: out = conv(in) + bias (+ res)
// ---------------------------------------------------------------------------
#define TILE_H 16
#define TILE_W 32
#define OCG 8
#define ICCH 8

__global__ __launch_bounds__(256) void conv3x3_dense(
    const float* __restrict__ in, const float* __restrict__ wgt,
    const float* __restrict__ bias, const float* __restrict__ res,
    float* __restrict__ outp, int add_res)
{
    __shared__ __align__(16) float ws[CC][3][3][OCG];        // 18.4 KB
    __shared__ float tile[ICCH][TILE_H + 2][TILE_W + 2];     // 19.6 KB

    const int tid = threadIdx.x;
    const int bw  = blockIdx.x * TILE_W;
    const int bh  = blockIdx.y * TILE_H;
    const int z   = blockIdx.z;
    const int ocg = z & 7;
    const int b   = z >> 3;

    // Preload all weights for this oc-group: ws[ic][ky][kx][o]
    for (int i = tid; i < CC * 9 * OCG; i += 256) {
        int o  = i & (OCG - 1);
        int r  = i / OCG;
        int k  = r % 9;
        int ic = r / 9;
        ws[ic][k / 3][k % 3][o] = wgt[((ocg * OCG + o) * CC + ic) * 9 + k];
    }

    const int tx = tid & 15;   // column pair index (0..15)
    const int ty = tid >> 4;   // row (0..15)

    float acc0[OCG], acc1[OCG];
#pragma unroll
    for (int o = 0; o < OCG; o++) { acc0[o] = 0.f; acc1[o] = 0.f; }

    __syncthreads();

    for (int ic0 = 0; ic0 < CC; ic0 += ICCH) {
        // cooperative load of 8 channels of the (TILE_H+2)x(TILE_W+2) halo tile
        for (int i = tid; i < ICCH * (TILE_H + 2) * (TILE_W + 2); i += 256) {
            int xcol = i % (TILE_W + 2);
            int r2   = i / (TILE_W + 2);
            int yrow = r2 % (TILE_H + 2);
            int c    = r2 / (TILE_H + 2);
            int gh = bh + yrow - 1;
            int gw = bw + xcol - 1;
            float v = 0.f;
            if ((unsigned)gh < (unsigned)HH && (unsigned)gw < (unsigned)WW)
                v = in[((b * CC + ic0 + c) * HH + gh) * WW + gw];
            tile[c][yrow][xcol] = v;
        }
        __syncthreads();

#pragma unroll
        for (int c = 0; c < ICCH; c++) {
            const int ic = ic0 + c;
            float n0[4], n1[4], n2[4];
#pragma unroll
            for (int cc = 0; cc < 4; cc++) {
                n0[cc] = tile[c][ty + 0][tx * 2 + cc];
                n1[cc] = tile[c][ty + 1][tx * 2 + cc];
                n2[cc] = tile[c][ty + 2][tx * 2 + cc];
            }
#pragma unroll
            for (int r = 0; r < 3; r++) {
                const float* nr = (r == 0) ? n0 : (r == 1) ? n1 : n2;
#pragma unroll
                for (int s = 0; s < 3; s++) {
                    float4 wa = *(const float4*)&ws[ic][r][s][0];
                    float4 wb = *(const float4*)&ws[ic][r][s][4];
                    float v0 = nr[s];
                    float v1 = nr[s + 1];
                    acc0[0] += wa.x * v0; acc0[1] += wa.y * v0;
                    acc0[2] += wa.z * v0; acc0[3] += wa.w * v0;
                    acc0[4] += wb.x * v0; acc0[5] += wb.y * v0;
                    acc0[6] += wb.z * v0; acc0[7] += wb.w * v0;
                    acc1[0] += wa.x * v1; acc1[1] += wa.y * v1;
                    acc1[2] += wa.z * v1; acc1[3] += wa.w * v1;
                    acc1[4] += wb.x * v1; acc1[5] += wb.y * v1;
                    acc1[6] += wb.z * v1; acc1[7] += wb.w * v1;
                }
            }
        }
        __syncthreads();
    }

    const int h  = bh + ty;
    const int w0c = bw + tx * 2;
#pragma unroll
    for (int o = 0; o < OCG; o++) {
        const int oc = ocg * OCG + o;
        const float bb = bias[oc];
        long base = ((long)(b * CC + oc) * HH + h) * WW;
        float v0 = acc0[o] + bb;
        float v1 = acc1[o] + bb;
        if (add_res) {
            v0 += res[base + w0c];
            v1 += res[base + w0c + 1];
        }
        outp[base + w0c]     = v0;
        outp[base + w0c + 1] = v1;
    }
}

// ---------------------------------------------------------------------------
// Per-(b,c) spatial mean of x0. Deterministic tree reduction.
// ---------------------------------------------------------------------------
__global__ __launch_bounds__(256) void mean_kernel(const float* __restrict__ x0,
                                                   float* __restrict__ mean)
{
    const int bc = blockIdx.x;
    const float4* p4 = (const float4*)(x0 + (long)bc * NPIX);
    float s = 0.f;
    for (int i = threadIdx.x; i < NPIX / 4; i += 256) {
        float4 v = p4[i];
        s += v.x + v.y + v.z + v.w;
    }
    __shared__ float red[256];
    red[threadIdx.x] = s;
    __syncthreads();
    for (int off = 128; off > 0; off >>= 1) {
        if (threadIdx.x < off) red[threadIdx.x] += red[threadIdx.x + off];
        __syncthreads();
    }
    if (threadIdx.x == 0) mean[bc] = red[0] * (1.f / (float)NPIX);
}

// ---------------------------------------------------------------------------
// ECA: 1D conv (kernel 3, pad 1) over channel axis of the means.
// ---------------------------------------------------------------------------
__global__ void eca_kernel(const float* __restrict__ mean,
                           const float* __restrict__ w2,
                           const float* __restrict__ b2,
                           float* __restrict__ x2o)
{
    const int t = threadIdx.x;  // 512 = BN*CC
    const int b = t >> 6, c = t & 63;
    float m0 = (c > 0)  ? mean[b * CC + c - 1] : 0.f;
    float m1 =            mean[b * CC + c];
    float m2 = (c < 63) ? mean[b * CC + c + 1] : 0.f;
    x2o[t] = w2[0] * m0 + w2[1] * m1 + w2[2] * m2 + b2[0];
}

// ---------------------------------------------------------------------------
// Depthwise 3x3 of x0 + b1 + x2[b,c] broadcast -> out1
// block = (h-chunk of 8 rows, c, b); 256 threads, 4 px/thread.
// ---------------------------------------------------------------------------
__global__ __launch_bounds__(256) void dw_kernel(
    const float* __restrict__ x0, const float* __restrict__ w1,
    const float* __restrict__ b1, const float* __restrict__ x2,
    float* __restrict__ outp)
{
    __shared__ float t[10][130];
    const int h0 = blockIdx.x * 8;
    const int c  = blockIdx.y;
    const int b  = blockIdx.z;
    const float* src = x0 + (long)(b * CC + c) * NPIX;

    for (int i = threadIdx.x; i < 10 * 130; i += 256) {
        int r = i / 130, col = i % 130;
        int gh = h0 - 1 + r, gw = col - 1;
        float v = 0.f;
        if ((unsigned)gh < (unsigned)HH && (unsigned)gw < (unsigned)WW)
            v = src[gh * WW + gw];
        t[r][col] = v;
    }
    float wk[9];
#pragma unroll
    for (int k = 0; k < 9; k++) wk[k] = w1[c * 9 + k];
    const float bb = b1[c] + x2[b * CC + c];
    __syncthreads();

    float* dst = outp + (long)(b * CC + c) * NPIX + (long)h0 * WW;
    for (int p = threadIdx.x; p < 8 * WW; p += 256) {
        int r = p / WW, wc = p % WW;
        float a = bb;
#pragma unroll
        for (int dy = 0; dy < 3; dy++)
#pragma unroll
            for (int dx = 0; dx < 3; dx++)
                a += wk[dy * 3 + dx] * t[r + dy][wc + dx];
        dst[p] = a;
    }
}

// ---------------------------------------------------------------------------
// Dynamic conv:
//   fil[b, c*9+k, h, w] = sum_c' w3[c*9+k, c'] * out1[b,c',h,w] + b3[c*9+k]
//   out2 = leaky( sum_k fil_k * x0[b,c,h-1+ky, w-1+kx] )
// block = (h-pair, b); 256 threads (2 rows x 128 cols).
// Each thread keeps its pixel's 64-ch out1 vector in registers; W3 rows
// streamed through smem as LDS.128 broadcasts (fil tensor never materialized).
// ---------------------------------------------------------------------------
__global__ __launch_bounds__(256) void dynconv_kernel(
    const float* __restrict__ out1, const float* __restrict__ x0,
    const float* __restrict__ w3, const float* __restrict__ b3,
    float* __restrict__ out2)
{
    __shared__ __align__(16) float w3s[9 * 64];
    __shared__ float b3s[9];
    __shared__ float x0s[4][130];

    const int tid = threadIdx.x;
    const int tx = tid & 127;
    const int ty = tid >> 7;
    const int h0 = blockIdx.x * 2;
    const int b  = blockIdx.y;
    const int h  = h0 + ty;

    float outv[64];
#pragma unroll
    for (int c2 = 0; c2 < 64; c2++)
        outv[c2] = out1[((long)(b * CC + c2) * HH + h) * WW + tx];

    for (int c = 0; c < CC; c++) {
        const float* w3c = w3 + (long)c * 9 * 64;  // rows c*9..c*9+8, contiguous
        for (int i = tid; i < 576; i += 256) w3s[i] = w3c[i];
        if (tid < 9) b3s[tid] = b3[c * 9 + tid];
        const float* x0c = x0 + (long)(b * CC + c) * NPIX;
        for (int i = tid; i < 4 * 130; i += 256) {
            int r = i / 130, j = i % 130;
            int gh = h0 - 1 + r, gw = j - 1;
            float v = 0.f;
            if ((unsigned)gh < (unsigned)HH && (unsigned)gw < (unsigned)WW)
                v = x0c[gh * WW + gw];
            x0s[r][j] = v;
        }
        __syncthreads();

        float s = 0.f;
#pragma unroll
        for (int k = 0; k < 9; k++) {
            float a = b3s[k];
#pragma unroll
            for (int c4 = 0; c4 < 64; c4 += 4) {
                float4 wv = *(const float4*)&w3s[k * 64 + c4];
                a += wv.x * outv[c4] + wv.y * outv[c4 + 1] +
                     wv.z * outv[c4 + 2] + wv.w * outv[c4 + 3];
            }
            const int dy = k / 3, dx = k % 3;
            s += a * x0s[ty + dy][tx + dx];
        }
        s = (s >= 0.f) ? s : 0.2f * s;
        out2[((long)(b * CC + c) * HH + h) * WW + tx] = s;
        __syncthreads();
    }
}

// ---------------------------------------------------------------------------
// Launch
// ---------------------------------------------------------------------------
extern "C" void kernel_launch(void* const* d_in, const int* in_sizes, int n_in,
                              void* d_out, int out_size)
{
    const float* x  = (const float*)d_in[0];
    const float* w0 = (const float*)d_in[1];
    const float* b0 = (const float*)d_in[2];
    const float* w1 = (const float*)d_in[3];
    const float* b1 = (const float*)d_in[4];
    const float* w2 = (const float*)d_in[5];
    const float* b2 = (const float*)d_in[6];
    const float* w3 = (const float*)d_in[7];
    const float* b3 = (const float*)d_in[8];
    const float* wf = (const float*)d_in[9];
    const float* bf = (const float*)d_in[10];
    float* out = (float*)d_out;

    float *px0, *pout1, *pout2, *pmean, *px2;
    cudaGetSymbolAddress((void**)&px0,   g_x0);
    cudaGetSymbolAddress((void**)&pout1, g_out1);
    cudaGetSymbolAddress((void**)&pout2, g_out2);
    cudaGetSymbolAddress((void**)&pmean, g_mean);
    cudaGetSymbolAddress((void**)&px2,   g_x2);

    dim3 cgrid(WW / TILE_W, HH / TILE_H, BN * (CC / OCG));

    // 1) conv0: x0 = conv3x3(x, w0) + b0
    conv3x3_dense<<<cgrid, 256>>>(x, w0, b0, nullptr, px0, 0);
    // 2) per-channel spatial mean of x0
    mean_kernel<<<BN * CC, 256>>>(px0, pmean);
    // 3) ECA conv1d over channel axis
    eca_kernel<<<1, BN * CC>>>(pmean, w2, b2, px2);
    // 4) out1 = depthwise3x3(x0) + b1 + x2 broadcast
    dw_kernel<<<dim3(HH / 8, CC, BN), 256>>>(px0, w1, b1, px2, pout1);
    // 5) out2 = leaky(dynamic conv of x0 with filters = W3 @ out1 + b3)
    dynconv_kernel<<<dim3(HH / 2, BN), 256>>>(pout1, px0, w3, b3, pout2);
    // 6) out = conv3x3(out2, wf) + bf + x
    conv3x3_dense<<<cgrid, 256>>>(pout2, wf, bf, x, out, 1);
}

// round 4
// speedup vs baseline: 1.0732x; 1.0732x over previous
#include <cuda_runtime.h>

// Problem constants
#define BN 8
#define CC 64
#define HH 128
#define WW 128
#define NPIX (HH * WW)

typedef unsigned long long u64;

// ---------------------------------------------------------------------------
// f32x2 packed-math helpers (sm_100+/sm_103a PTX)
// ---------------------------------------------------------------------------
__device__ __forceinline__ u64 pk2(float lo, float hi) {
    u64 r; asm("mov.b64 %0, {%1, %2};" : "=l"(r) : "f"(lo), "f"(hi)); return r;
}
__device__ __forceinline__ void fma2(u64& d, u64 a, u64 b) {
    asm("fma.rn.f32x2 %0, %1, %2, %0;" : "+l"(d) : "l"(a), "l"(b));
}
__device__ __forceinline__ u64 add2(u64 a, u64 b) {
    u64 r; asm("add.rn.f32x2 %0, %1, %2;" : "=l"(r) : "l"(a), "l"(b)); return r;
}
__device__ __forceinline__ float2 up2(u64 v) {
    float2 f; asm("mov.b64 {%0, %1}, %2;" : "=f"(f.x), "=f"(f.y) : "l"(v)); return f;
}

// ---------------------------------------------------------------------------
// Scratch (device globals — no allocation allowed in kernel_launch)
// ---------------------------------------------------------------------------
__device__ float g_x0[BN * CC * NPIX];    // conv0 output
__device__ float g_out1[BN * CC * NPIX];  // depthwise + channel-attn output
__device__ float g_out2[BN * CC * NPIX];  // dynamic conv + leaky output
__device__ float g_mean[BN * CC];
__device__ float g_x2[BN * CC];

// ---------------------------------------------------------------------------
// Dense 3x3 conv, C=64 -> 64, pad 1.  Register-tiled + f32x2 packed FMA:
//   block = 256 threads, tile 32(W) x 16(H), 8 output channels per block.
//   thread = 2 adjacent W pixels x 4 packed oc-pair accumulators each.
//   Weights (8 oc x 64 ic x 9) in smem, read as ulonglong2 (LDS.128 bcast).
// ---------------------------------------------------------------------------
#define TILE_H 16
#define TILE_W 32
#define OCG 8
#define ICCH 8

__global__ __launch_bounds__(256) void conv3x3_dense(
    const float* __restrict__ in, const float* __restrict__ wgt,
    const float* __restrict__ bias, const float* __restrict__ res,
    float* __restrict__ outp, int add_res)
{
    __shared__ __align__(16) float ws[CC][3][3][OCG];        // 18.4 KB
    __shared__ float tile[ICCH][TILE_H + 2][TILE_W + 2];     // 19.6 KB

    const int tid = threadIdx.x;
    const int bw  = blockIdx.x * TILE_W;
    const int bh  = blockIdx.y * TILE_H;
    const int z   = blockIdx.z;
    const int ocg = z & 7;
    const int b   = z >> 3;

    // Preload all weights for this oc-group: ws[ic][ky][kx][o]
    for (int i = tid; i < CC * 9 * OCG; i += 256) {
        int o  = i & (OCG - 1);
        int r  = i / OCG;
        int k  = r % 9;
        int ic = r / 9;
        ws[ic][k / 3][k % 3][o] = wgt[((ocg * OCG + o) * CC + ic) * 9 + k];
    }

    const int tx = tid & 15;   // column-pair index (0..15)
    const int ty = tid >> 4;   // row (0..15)

    u64 a0[4], a1[4];          // oc-pair accumulators for px0 / px1
#pragma unroll
    for (int j = 0; j < 4; j++) { a0[j] = 0ull; a1[j] = 0ull; }

    __syncthreads();

    for (int ic0 = 0; ic0 < CC; ic0 += ICCH) {
        // cooperative load of 8 channels of the (TILE_H+2)x(TILE_W+2) halo tile
        for (int i = tid; i < ICCH * (TILE_H + 2) * (TILE_W + 2); i += 256) {
            int xcol = i % (TILE_W + 2);
            int r2   = i / (TILE_W + 2);
            int yrow = r2 % (TILE_H + 2);
            int c    = r2 / (TILE_H + 2);
            int gh = bh + yrow - 1;
            int gw = bw + xcol - 1;
            float v = 0.f;
            if ((unsigned)gh < (unsigned)HH && (unsigned)gw < (unsigned)WW)
                v = in[((b * CC + ic0 + c) * HH + gh) * WW + gw];
            tile[c][yrow][xcol] = v;
        }
        __syncthreads();

#pragma unroll
        for (int c = 0; c < ICCH; c++) {
            const int ic = ic0 + c;
            // duplicated (dup-packed) neighborhood values, 4 per row
            u64 n0[4], n1[4], n2[4];
#pragma unroll
            for (int cc = 0; cc < 4; cc++) {
                float v0 = tile[c][ty + 0][tx * 2 + cc];
                float v1 = tile[c][ty + 1][tx * 2 + cc];
                float v2 = tile[c][ty + 2][tx * 2 + cc];
                n0[cc] = pk2(v0, v0);
                n1[cc] = pk2(v1, v1);
                n2[cc] = pk2(v2, v2);
            }
#pragma unroll
            for (int r = 0; r < 3; r++) {
                const u64* nr = (r == 0) ? n0 : (r == 1) ? n1 : n2;
#pragma unroll
                for (int s = 0; s < 3; s++) {
                    ulonglong2 wA = *(const ulonglong2*)&ws[ic][r][s][0]; // oc0..3
                    ulonglong2 wB = *(const ulonglong2*)&ws[ic][r][s][4]; // oc4..7
                    u64 v0 = nr[s];
                    u64 v1 = nr[s + 1];
                    fma2(a0[0], wA.x, v0); fma2(a0[1], wA.y, v0);
                    fma2(a0[2], wB.x, v0); fma2(a0[3], wB.y, v0);
                    fma2(a1[0], wA.x, v1); fma2(a1[1], wA.y, v1);
                    fma2(a1[2], wB.x, v1); fma2(a1[3], wB.y, v1);
                }
            }
        }
        __syncthreads();
    }

    const int h   = bh + ty;
    const int w0c = bw + tx * 2;
#pragma unroll
    for (int j = 0; j < 4; j++) {
        float2 p0 = up2(a0[j]);
        float2 p1 = up2(a1[j]);
#pragma unroll
        for (int half = 0; half < 2; half++) {
            const int oc = ocg * OCG + 2 * j + half;
            const float bb = bias[oc];
            long base = ((long)(b * CC + oc) * HH + h) * WW;
            float v0 = (half ? p0.y : p0.x) + bb;
            float v1 = (half ? p1.y : p1.x) + bb;
            if (add_res) {
                v0 += res[base + w0c];
                v1 += res[base + w0c + 1];
            }
            outp[base + w0c]     = v0;
            outp[base + w0c + 1] = v1;
        }
    }
}

// ---------------------------------------------------------------------------
// Per-(b,c) spatial mean of x0. Deterministic tree reduction.
// ---------------------------------------------------------------------------
__global__ __launch_bounds__(256) void mean_kernel(const float* __restrict__ x0,
                                                   float* __restrict__ mean)
{
    const int bc = blockIdx.x;
    const float4* p4 = (const float4*)(x0 + (long)bc * NPIX);
    float s = 0.f;
    for (int i = threadIdx.x; i < NPIX / 4; i += 256) {
        float4 v = p4[i];
        s += v.x + v.y + v.z + v.w;
    }
    __shared__ float red[256];
    red[threadIdx.x] = s;
    __syncthreads();
    for (int off = 128; off > 0; off >>= 1) {
        if (threadIdx.x < off) red[threadIdx.x] += red[threadIdx.x + off];
        __syncthreads();
    }
    if (threadIdx.x == 0) mean[bc] = red[0] * (1.f / (float)NPIX);
}

// ---------------------------------------------------------------------------
// ECA: 1D conv (kernel 3, pad 1) over channel axis of the means.
// ---------------------------------------------------------------------------
__global__ void eca_kernel(const float* __restrict__ mean,
                           const float* __restrict__ w2,
                           const float* __restrict__ b2,
                           float* __restrict__ x2o)
{
    const int t = threadIdx.x;  // 512 = BN*CC
    const int b = t >> 6, c = t & 63;
    float m0 = (c > 0)  ? mean[b * CC + c - 1] : 0.f;
    float m1 =            mean[b * CC + c];
    float m2 = (c < 63) ? mean[b * CC + c + 1] : 0.f;
    x2o[t] = w2[0] * m0 + w2[1] * m1 + w2[2] * m2 + b2[0];
}

// ---------------------------------------------------------------------------
// Depthwise 3x3 of x0 + b1 + x2[b,c] broadcast -> out1
// ---------------------------------------------------------------------------
__global__ __launch_bounds__(256) void dw_kernel(
    const float* __restrict__ x0, const float* __restrict__ w1,
    const float* __restrict__ b1, const float* __restrict__ x2,
    float* __restrict__ outp)
{
    __shared__ float t[10][130];
    const int h0 = blockIdx.x * 8;
    const int c  = blockIdx.y;
    const int b  = blockIdx.z;
    const float* src = x0 + (long)(b * CC + c) * NPIX;

    for (int i = threadIdx.x; i < 10 * 130; i += 256) {
        int r = i / 130, col = i % 130;
        int gh = h0 - 1 + r, gw = col - 1;
        float v = 0.f;
        if ((unsigned)gh < (unsigned)HH && (unsigned)gw < (unsigned)WW)
            v = src[gh * WW + gw];
        t[r][col] = v;
    }
    float wk[9];
#pragma unroll
    for (int k = 0; k < 9; k++) wk[k] = w1[c * 9 + k];
    const float bb = b1[c] + x2[b * CC + c];
    __syncthreads();

    float* dst = outp + (long)(b * CC + c) * NPIX + (long)h0 * WW;
    for (int p = threadIdx.x; p < 8 * WW; p += 256) {
        int r = p / WW, wc = p % WW;
        float a = bb;
#pragma unroll
        for (int dy = 0; dy < 3; dy++)
#pragma unroll
            for (int dx = 0; dx < 3; dx++)
                a += wk[dy * 3 + dx] * t[r + dy][wc + dx];
        dst[p] = a;
    }
}

// ---------------------------------------------------------------------------
// Dynamic conv (f32x2 packed):
//   fil[b, c*9+k, h, w] = sum_c' w3[c*9+k, c'] * out1[b,c',h,w] + b3[c*9+k]
//   out2 = leaky( sum_k fil_k * x0[b,c,h-1+ky, w-1+kx] )
// block = (h-pair, b); 256 threads (2 rows x 128 cols).
// Each thread caches its pixel's 64-ch out1 vector as 32 packed pairs in
// registers; W3 rows stream through smem as ulonglong2 (LDS.128 broadcast).
// ---------------------------------------------------------------------------
__global__ __launch_bounds__(256) void dynconv_kernel(
    const float* __restrict__ out1, const float* __restrict__ x0,
    const float* __restrict__ w3, const float* __restrict__ b3,
    float* __restrict__ out2)
{
    __shared__ __align__(16) float w3s[9 * 64];
    __shared__ float b3s[9];
    __shared__ float x0s[4][130];

    const int tid = threadIdx.x;
    const int tx = tid & 127;
    const int ty = tid >> 7;
    const int h0 = blockIdx.x * 2;
    const int b  = blockIdx.y;
    const int h  = h0 + ty;

    // pack the 64-channel out1 vector of this pixel into 32 f32x2 pairs
    u64 ov[32];
#pragma unroll
    for (int c2 = 0; c2 < 32; c2++) {
        float lo = out1[((long)(b * CC + 2 * c2)     * HH + h) * WW + tx];
        float hi = out1[((long)(b * CC + 2 * c2 + 1) * HH + h) * WW + tx];
        ov[c2] = pk2(lo, hi);
    }

    for (int c = 0; c < CC; c++) {
        const float* w3c = w3 + (long)c * 9 * 64;  // rows c*9..c*9+8, contiguous
        for (int i = tid; i < 576; i += 256) w3s[i] = w3c[i];
        if (tid < 9) b3s[tid] = b3[c * 9 + tid];
        const float* x0c = x0 + (long)(b * CC + c) * NPIX;
        for (int i = tid; i < 4 * 130; i += 256) {
            int r = i / 130, j = i % 130;
            int gh = h0 - 1 + r, gw = j - 1;
            float v = 0.f;
            if ((unsigned)gh < (unsigned)HH && (unsigned)gw < (unsigned)WW)
                v = x0c[gh * WW + gw];
            x0s[r][j] = v;
        }
        __syncthreads();

        float s = 0.f;
#pragma unroll
        for (int k = 0; k < 9; k++) {
            const ulonglong2* wp = (const ulonglong2*)&w3s[k * 64];
            u64 q0 = 0ull, q1 = 0ull, q2 = 0ull, q3 = 0ull;
#pragma unroll
            for (int j = 0; j < 8; j++) {          // 16 ulonglong2 = 32 pairs
                ulonglong2 wv0 = wp[2 * j];
                ulonglong2 wv1 = wp[2 * j + 1];
                fma2(q0, wv0.x, ov[4 * j + 0]);
                fma2(q1, wv0.y, ov[4 * j + 1]);
                fma2(q2, wv1.x, ov[4 * j + 2]);
                fma2(q3, wv1.y, ov[4 * j + 3]);
            }
            float2 p = up2(add2(add2(q0, q1), add2(q2, q3)));
            float a = b3s[k] + p.x + p.y;
            const int dy = k / 3, dx = k % 3;
            s += a * x0s[ty + dy][tx + dx];
        }
        s = (s >= 0.f) ? s : 0.2f * s;
        out2[((long)(b * CC + c) * HH + h) * WW + tx] = s;
        __syncthreads();
    }
}

// ---------------------------------------------------------------------------
// Launch
// ---------------------------------------------------------------------------
extern "C" void kernel_launch(void* const* d_in, const int* in_sizes, int n_in,
                              void* d_out, int out_size)
{
    const float* x  = (const float*)d_in[0];
    const float* w0 = (const float*)d_in[1];
    const float* b0 = (const float*)d_in[2];
    const float* w1 = (const float*)d_in[3];
    const float* b1 = (const float*)d_in[4];
    const float* w2 = (const float*)d_in[5];
    const float* b2 = (const float*)d_in[6];
    const float* w3 = (const float*)d_in[7];
    const float* b3 = (const float*)d_in[8];
    const float* wf = (const float*)d_in[9];
    const float* bf = (const float*)d_in[10];
    float* out = (float*)d_out;

    float *px0, *pout1, *pout2, *pmean, *px2;
    cudaGetSymbolAddress((void**)&px0,   g_x0);
    cudaGetSymbolAddress((void**)&pout1, g_out1);
    cudaGetSymbolAddress((void**)&pout2, g_out2);
    cudaGetSymbolAddress((void**)&pmean, g_mean);
    cudaGetSymbolAddress((void**)&px2,   g_x2);

    dim3 cgrid(WW / TILE_W, HH / TILE_H, BN * (CC / OCG));

    // 1) conv0: x0 = conv3x3(x, w0) + b0
    conv3x3_dense<<<cgrid, 256>>>(x, w0, b0, nullptr, px0, 0);
    // 2) per-channel spatial mean of x0
    mean_kernel<<<BN * CC, 256>>>(px0, pmean);
    // 3) ECA conv1d over channel axis
    eca_kernel<<<1, BN * CC>>>(pmean, w2, b2, px2);
    // 4) out1 = depthwise3x3(x0) + b1 + x2 broadcast
    dw_kernel<<<dim3(HH / 8, CC, BN), 256>>>(px0, w1, b1, px2, pout1);
    // 5) out2 = leaky(dynamic conv of x0 with filters = W3 @ out1 + b3)
    dynconv_kernel<<<dim3(HH / 2, BN), 256>>>(pout1, px0, w3, b3, pout2);
    // 6) out = conv3x3(out2, wf) + bf + x
    conv3x3_dense<<<cgrid, 256>>>(pout2, wf, bf, x, out, 1);
}